// round 1
// baseline (speedup 1.0000x reference)
#include <cuda_runtime.h>

// Gaussian-splat render:
//   out[n,c] = sum_m exp(-0.5 * d^T C_m^-1 d) * cols[m,c],  d = x[n] - mu[m]
//
// Strategy (compute-bound, FMA+MUFU co-limited):
//  * Expand Mahalanobis form into 6 per-Gaussian coefficients over pixel
//    features (x^2, xy, y^2, x, y, 1), pre-scaled by -0.5*log2(e) so the
//    weight is a single ex2.approx.
//  * Pack 2 pixels per thread in f32x2 registers; hot loop uses
//    fma.rn.f32x2 (2x fp32 FMA throughput on sm_103a).
//  * Coefficients + colors stored lane-duplicated in shared memory
//    (ulonglong2 = LDS.128 yields ready-to-use packed operands, no MOVs).
//  * 148 CTAs (one per SM), round-robin pair assignment for load balance.

typedef unsigned long long u64;

static constexpr int N_GAUSS = 2048;
static constexpr int N_PAIR  = 32768;   // 65536 pixels / 2
static constexpr int BLK     = 256;
static constexpr int GRID    = 148;
// per-Gaussian smem: 10 u64 slots (9 used: cxx,cxy,cyy,cx,cy,c0,r,g,b + pad)
static constexpr int SLOTS   = 10;
static constexpr size_t SMEM_BYTES = (size_t)N_GAUSS * SLOTS * sizeof(u64);

__device__ __forceinline__ u64 pack2(float lo, float hi) {
    u64 r;
    asm("mov.b64 %0, {%1, %2};" : "=l"(r) : "f"(lo), "f"(hi));
    return r;
}
__device__ __forceinline__ void unpack2(u64 v, float& lo, float& hi) {
    asm("mov.b64 {%0, %1}, %2;" : "=f"(lo), "=f"(hi) : "l"(v));
}
__device__ __forceinline__ u64 fma2(u64 a, u64 b, u64 c) {
    u64 d;
    asm("fma.rn.f32x2 %0, %1, %2, %3;" : "=l"(d) : "l"(a), "l"(b), "l"(c));
    return d;
}
__device__ __forceinline__ u64 mul2(u64 a, u64 b) {
    u64 d;
    asm("mul.rn.f32x2 %0, %1, %2;" : "=l"(d) : "l"(a), "l"(b));
    return d;
}
__device__ __forceinline__ float ex2f(float v) {
    float r;
    asm("ex2.approx.f32 %0, %1;" : "=f"(r) : "f"(v));
    return r;
}

__global__ __launch_bounds__(BLK, 1)
void render_kernel(const float* __restrict__ x,
                   const float* __restrict__ mus,
                   const float* __restrict__ covs,
                   const float* __restrict__ cols,
                   float* __restrict__ out)
{
    extern __shared__ u64 sh[];
    const int tid = threadIdx.x;

    // ---- Build lane-duplicated coefficient table in shared memory ----
    // maha = p00*dx^2 + 2*p01*dx*dy + p11*dy^2 with P = C^-1.
    // Expanded over (xx, xy, yy, x, y, 1) and pre-scaled by s = -0.5*log2(e):
    //   w = ex2( cxx*xx + cxy*xy + cyy*yy + cx*x + cy*y + c0 )
    const float s = -0.72134752044448170368f;  // -0.5 * log2(e)
    for (int m = tid; m < N_GAUSS; m += BLK) {
        float2 mu = ((const float2*)mus)[m];
        float4 cv = ((const float4*)covs)[m];     // [a, b, b, c]
        float a = cv.x, b = cv.y, c = cv.w;
        float inv_det = 1.0f / (a * c - b * b);
        float p00 =  c * inv_det;
        float p01 = -b * inv_det;
        float p11 =  a * inv_det;

        float cxx = s * p00;
        float cxy = s * (2.0f * p01);
        float cyy = s * p11;
        float l1 = p00 * mu.x + p01 * mu.y;
        float l2 = p01 * mu.x + p11 * mu.y;
        float cx = s * (-2.0f * l1);
        float cy = s * (-2.0f * l2);
        float c0 = s * (mu.x * l1 + mu.y * l2);

        float r = cols[3 * m + 0];
        float g = cols[3 * m + 1];
        float bl = cols[3 * m + 2];

        u64* q = sh + (size_t)m * SLOTS;
        q[0] = pack2(cxx, cxx);
        q[1] = pack2(cxy, cxy);
        q[2] = pack2(cyy, cyy);
        q[3] = pack2(cx,  cx);
        q[4] = pack2(cy,  cy);
        q[5] = pack2(c0,  c0);
        q[6] = pack2(r,   r);
        q[7] = pack2(g,   g);
        q[8] = pack2(bl,  bl);
        q[9] = 0ull;
    }
    __syncthreads();

    // ---- Round-robin pair assignment: all 148 SMs get ~221 pairs ----
    const int p = blockIdx.x + gridDim.x * tid;
    if (p >= N_PAIR) return;

    // pixels 2p and 2p+1: x is [N,2] row-major -> one float4 covers both
    float4 xv = ((const float4*)x)[p];
    u64 X1 = pack2(xv.x, xv.z);
    u64 X2 = pack2(xv.y, xv.w);
    u64 XX = mul2(X1, X1);
    u64 XY = mul2(X1, X2);
    u64 YY = mul2(X2, X2);

    u64 aR = 0ull, aG = 0ull, aB = 0ull;  // packed {0.f, 0.f}

    const ulonglong2* S = (const ulonglong2*)sh;  // 5 LDS.128 per Gaussian
    #pragma unroll 4
    for (int m = 0; m < N_GAUSS; ++m) {
        ulonglong2 v0 = S[m * 5 + 0];  // {cxx,cxx} {cxy,cxy}
        ulonglong2 v1 = S[m * 5 + 1];  // {cyy,cyy} {cx, cx }
        ulonglong2 v2 = S[m * 5 + 2];  // {cy, cy } {c0, c0 }
        ulonglong2 v3 = S[m * 5 + 3];  // {r,  r  } {g,  g  }
        ulonglong2 v4 = S[m * 5 + 4];  // {b,  b  } {pad    }

        u64 t = v2.y;                  // c0
        t = fma2(v0.x, XX, t);
        t = fma2(v0.y, XY, t);
        t = fma2(v1.x, YY, t);
        t = fma2(v1.y, X1, t);
        t = fma2(v2.x, X2, t);

        float tl, th;
        unpack2(t, tl, th);
        u64 w = pack2(ex2f(tl), ex2f(th));

        aR = fma2(v3.x, w, aR);
        aG = fma2(v3.y, w, aG);
        aB = fma2(v4.x, w, aB);
    }

    float r0, r1, g0, g1, b0, b1;
    unpack2(aR, r0, r1);
    unpack2(aG, g0, g1);
    unpack2(aB, b0, b1);

    float* o = out + (size_t)p * 6;    // pixel 2p then 2p+1, 3 channels each
    o[0] = r0; o[1] = g0; o[2] = b0;
    o[3] = r1; o[4] = g1; o[5] = b1;
}

extern "C" void kernel_launch(void* const* d_in, const int* in_sizes, int n_in,
                              void* d_out, int out_size)
{
    const float* x    = (const float*)d_in[0];
    const float* mus  = (const float*)d_in[1];
    const float* covs = (const float*)d_in[2];
    const float* cols = (const float*)d_in[3];
    float* out = (float*)d_out;

    cudaFuncSetAttribute(render_kernel,
                         cudaFuncAttributeMaxDynamicSharedMemorySize,
                         (int)SMEM_BYTES);
    render_kernel<<<GRID, BLK, SMEM_BYTES>>>(x, mus, covs, cols, out);
}